// round 5
// baseline (speedup 1.0000x reference)
#include <cuda_runtime.h>
#include <cstdint>

// Problem constants
#define T_STEPS 1024
#define BATCH   32
#define DIM     1024
#define NH      64
#define NTOT    256                 // 4 * NH (k | v | q | ax)
#define M_TOTAL (T_STEPS * BATCH)   // 32768

// Scratch: projections Y[m][256], m = t*BATCH+b  (32 MB)
__device__ float g_y[(size_t)M_TOTAL * NTOT];
// Precomputed per-(t,b) dot scalars, 8 floats each (1 MB):
// {KK1[t], KK2[t+1], KK3[t+2], KQ0[t], KQ1[t], KQ2[t+1], KQ3[t+2], 0}
__device__ float g_pc[(size_t)M_TOTAL * 8];

// ---------------- GEMM (tf32 mma.sync), 512 threads, 2x occupancy ----------------
#define BM 128
#define BK 16
#define STAGES 3
#define XS_STRIDE 20
#define X_TILE_F (BM * XS_STRIDE)
#define W_TILE_F (NTOT * XS_STRIDE)
#define STAGE_F  (X_TILE_F + W_TILE_F)
#define SMEM_BYTES (STAGES * STAGE_F * 4)

__device__ __forceinline__ void cp_async16(uint32_t saddr, const void* gptr) {
    asm volatile("cp.async.cg.shared.global [%0], [%1], 16;\n" :: "r"(saddr), "l"(gptr));
}
__device__ __forceinline__ uint32_t f2tf32(float f) {
    uint32_t r;
    asm("cvt.rna.tf32.f32 %0, %1;" : "=r"(r) : "f"(f));
    return r;
}
__device__ __forceinline__ void mma_tf32(float* c, const uint32_t* a, const uint32_t* b) {
    asm volatile(
        "mma.sync.aligned.m16n8k8.row.col.f32.tf32.tf32.f32 "
        "{%0,%1,%2,%3}, {%4,%5,%6,%7}, {%8,%9}, {%0,%1,%2,%3};"
        : "+f"(c[0]), "+f"(c[1]), "+f"(c[2]), "+f"(c[3])
        : "r"(a[0]), "r"(a[1]), "r"(a[2]), "r"(a[3]), "r"(b[0]), "r"(b[1]));
}

__global__ __launch_bounds__(512, 1)
void proj_gemm(const float* __restrict__ X,
               const float* __restrict__ Wk, const float* __restrict__ Wv,
               const float* __restrict__ Wq, const float* __restrict__ Wa)
{
    extern __shared__ float smem[];
    const int tid = threadIdx.x;
    const int m0  = blockIdx.x * BM;

    const float* wptr[4] = {Wk, Wv, Wq, Wa};

    // X: 1 float4/thread/stage (512*4 = 2048 = X tile)
    const int xrow = tid >> 2, xc4 = tid & 3;
    const float* xg = X + (size_t)(m0 + xrow) * DIM + xc4 * 4;
    const uint32_t xs_off = (uint32_t)(xrow * XS_STRIDE + xc4 * 4);

    // W: 2 float4/thread/stage (1024 = W tile)
    const float* wg[2];
    uint32_t ws_off[2];
#pragma unroll
    for (int l = 0; l < 2; l++) {
        int f = tid + l * 512;
        int row = f >> 2, c4 = f & 3;
        wg[l] = wptr[row >> 6] + (size_t)(row & 63) * DIM + c4 * 4;
        ws_off[l] = (uint32_t)(X_TILE_F + row * XS_STRIDE + c4 * 4);
    }
    uint32_t smem_base = (uint32_t)__cvta_generic_to_shared(smem);

    const int lane = tid & 31;
    const int w    = tid >> 5;    // 0..15
    const int g    = lane >> 2;
    const int q    = lane & 3;
    const int wm   = w >> 2;      // 0..3 : 32-row slab
    const int wn   = w & 3;       // 0..3 : 64-col slab

    float acc[2][8][4];
#pragma unroll
    for (int mi = 0; mi < 2; mi++)
#pragma unroll
        for (int ni = 0; ni < 8; ni++)
#pragma unroll
            for (int r = 0; r < 4; r++) acc[mi][ni][r] = 0.0f;

    const int NITER = DIM / BK;

#pragma unroll
    for (int s = 0; s < STAGES - 1; s++) {
        uint32_t sb = smem_base + (uint32_t)((s % STAGES) * STAGE_F * 4);
        int koff = s * BK;
        cp_async16(sb + xs_off * 4, xg + koff);
#pragma unroll
        for (int l = 0; l < 2; l++) cp_async16(sb + ws_off[l] * 4, wg[l] + koff);
        asm volatile("cp.async.commit_group;\n");
    }

    for (int k = 0; k < NITER; k++) {
        asm volatile("cp.async.wait_group %0;\n" :: "n"(STAGES - 2));
        __syncthreads();

        int nk = k + STAGES - 1;
        if (nk < NITER) {
            uint32_t sb = smem_base + (uint32_t)((nk % STAGES) * STAGE_F * 4);
            int koff = nk * BK;
            cp_async16(sb + xs_off * 4, xg + koff);
#pragma unroll
            for (int l = 0; l < 2; l++) cp_async16(sb + ws_off[l] * 4, wg[l] + koff);
        }
        asm volatile("cp.async.commit_group;\n");

        const float* Xs = smem + (k % STAGES) * STAGE_F;
        const float* Ws = Xs + X_TILE_F;

#pragma unroll
        for (int kk = 0; kk < BK; kk += 8) {
            uint32_t a[2][4], bf[8][2];
#pragma unroll
            for (int mi = 0; mi < 2; mi++) {
                int r = wm * 32 + mi * 16 + g;
                a[mi][0] = f2tf32(Xs[r * XS_STRIDE + kk + q]);
                a[mi][1] = f2tf32(Xs[(r + 8) * XS_STRIDE + kk + q]);
                a[mi][2] = f2tf32(Xs[r * XS_STRIDE + kk + q + 4]);
                a[mi][3] = f2tf32(Xs[(r + 8) * XS_STRIDE + kk + q + 4]);
            }
#pragma unroll
            for (int ni = 0; ni < 8; ni++) {
                int r = wn * 64 + ni * 8 + g;
                bf[ni][0] = f2tf32(Ws[r * XS_STRIDE + kk + q]);
                bf[ni][1] = f2tf32(Ws[r * XS_STRIDE + kk + q + 4]);
            }
#pragma unroll
            for (int mi = 0; mi < 2; mi++)
#pragma unroll
                for (int ni = 0; ni < 8; ni++)
                    mma_tf32(acc[mi][ni], a[mi], bf[ni]);
        }
    }

#pragma unroll
    for (int mi = 0; mi < 2; mi++) {
#pragma unroll
        for (int ni = 0; ni < 8; ni++) {
            int m = m0 + wm * 32 + mi * 16 + g;
            int c = wn * 64 + ni * 8 + q * 2;
            float2 v0 = make_float2(acc[mi][ni][0], acc[mi][ni][1]);
            float2 v1 = make_float2(acc[mi][ni][2], acc[mi][ni][3]);
            *reinterpret_cast<float2*>(&g_y[(size_t)m * NTOT + c]) = v0;
            *reinterpret_cast<float2*>(&g_y[(size_t)(m + 8) * NTOT + c]) = v1;
        }
    }
}

// ---------------- Precompute k.k / k.q scalars ----------------
__device__ __forceinline__ float wsum32(float v) {
    v += __shfl_xor_sync(0xffffffffu, v, 16);
    v += __shfl_xor_sync(0xffffffffu, v, 8);
    v += __shfl_xor_sync(0xffffffffu, v, 4);
    v += __shfl_xor_sync(0xffffffffu, v, 2);
    v += __shfl_xor_sync(0xffffffffu, v, 1);
    return v;
}

__global__ __launch_bounds__(256, 2)
void precomp_kernel()
{
    int gw = (blockIdx.x * blockDim.x + threadIdx.x) >> 5;   // 0..32767
    int lane = threadIdx.x & 31;
    int t = gw >> 5, b = gw & 31;
    int e = lane * 2;

    const float* y = g_y;
    auto ldk = [&](int tt) -> float2 {
        return *reinterpret_cast<const float2*>(&y[(size_t)(tt * BATCH + b) * NTOT + e]);
    };
    auto ldq = [&](int tt) -> float2 {
        return *reinterpret_cast<const float2*>(&y[(size_t)(tt * BATCH + b) * NTOT + 128 + e]);
    };

    int t1 = t + 1 < T_STEPS ? t + 1 : T_STEPS - 1;
    int t2 = t + 2 < T_STEPS ? t + 2 : T_STEPS - 1;

    float2 km1 = (t > 0) ? ldk(t - 1) : make_float2(0.f, 0.f);
    float2 k0 = ldk(t), k1 = ldk(t1), k2 = ldk(t2);
    float2 q0 = ldq(t), q1 = ldq(t1), q2 = ldq(t2);

    float kk1 = wsum32(fmaf(km1.x, k0.x, km1.y * k0.y));
    float kk2 = wsum32(fmaf(km1.x, k1.x, km1.y * k1.y));
    float kk3 = wsum32(fmaf(km1.x, k2.x, km1.y * k2.y));
    float kq0 = wsum32(fmaf(k0.x,  q0.x, k0.y  * q0.y));
    float kq1 = wsum32(fmaf(km1.x, q0.x, km1.y * q0.y));
    float kq2 = wsum32(fmaf(km1.x, q1.x, km1.y * q1.y));
    float kq3 = wsum32(fmaf(km1.x, q2.x, km1.y * q2.y));

    if (lane == 0) {
        float* p = &g_pc[(size_t)gw * 8];
        *reinterpret_cast<float4*>(p)     = make_float4(kk1, kk2, kk3, kq0);
        *reinterpret_cast<float4*>(p + 4) = make_float4(kq1, kq2, kq3, 0.f);
    }
}

// ---------------- Scan v5: bfly8 (shfl), 8 warps/block, descriptor prefetch ----------------
#define SLOT_F 200           // per-t smem floats: kq[128] v[32] ax[32] pc[8]
#define RING   32            // t-slots resident (4 groups of 8)
#define SCAN_SMEM (RING * SLOT_F * 4)   // 102400 B

__device__ __forceinline__ float bfly8(float v) {
    v += __shfl_xor_sync(0xffffffffu, v, 4);
    v += __shfl_xor_sync(0xffffffffu, v, 2);
    v += __shfl_xor_sync(0xffffffffu, v, 1);
    return v;
}
__device__ __forceinline__ float dot8(float4 a0, float4 a1, float4 b0, float4 b1) {
    float p = a0.x * b0.x;
    p = fmaf(a0.y, b0.y, p); p = fmaf(a0.z, b0.z, p); p = fmaf(a0.w, b0.w, p);
    p = fmaf(a1.x, b1.x, p); p = fmaf(a1.y, b1.y, p);
    p = fmaf(a1.z, b1.z, p); p = fmaf(a1.w, b1.w, p);
    return p;
}
__device__ __forceinline__ float fsig(float z) {
    return __fdividef(1.0f, 1.0f + __expf(-z));
}

__global__ __launch_bounds__(256, 1)
void scan_kernel(const float* __restrict__ S0,
                 const float* __restrict__ d_alpha,
                 const float* __restrict__ b_alpha,
                 float* __restrict__ out)
{
    extern __shared__ float sm[];

    const int tid  = threadIdx.x;
    const int b    = blockIdx.y;
    const int i0   = blockIdx.x * 32;
    const int lane = tid & 31;
    const int w    = tid >> 5;            // 0..7
    const int r    = lane >> 3;           // row-in-warp 0..3
    const int j8   = lane & 7;            // 8 lanes per row
    const int i    = i0 + w * 4 + r;      // global row 0..63
    const int c0   = j8 * 8;              // column base (8 elems/lane)
    const int il   = i - i0;              // 0..31

    // ---- Precompute 2 prefetch descriptors/thread (50 float4 fields per t) ----
    // f<32: k|q  f<40: v-slice  f<48: ax-slice  f<50: pc
    const float* dsrc[2];
    int dstride[2], ddst[2], dtl[2];
    bool dvalid[2];
#pragma unroll
    for (int l = 0; l < 2; l++) {
        int c = tid + l * 256;
        dvalid[l] = (c < 400);
        int tl = c / 50, f = c - tl * 50;
        dtl[l] = tl;
        int srcoff, dstf;
        if (f < 32)      { srcoff = (f < 16 ? f * 4 : 128 + (f - 16) * 4); dstf = f * 4; }
        else if (f < 40) { srcoff = 64  + i0 + (f - 32) * 4; dstf = 128 + (f - 32) * 4; }
        else if (f < 48) { srcoff = 192 + i0 + (f - 40) * 4; dstf = 160 + (f - 40) * 4; }
        else             { srcoff = (f - 48) * 4;            dstf = 192 + (f - 48) * 4; }
        if (f < 48) { dsrc[l] = g_y  + (size_t)b * NTOT + srcoff; dstride[l] = BATCH * NTOT; }
        else        { dsrc[l] = g_pc + (size_t)b * 8    + srcoff; dstride[l] = BATCH * 8;  }
        ddst[l] = tl * SLOT_F + dstf;
    }
    uint32_t smb = (uint32_t)__cvta_generic_to_shared(sm);

    auto issue_group = [&](int gidx) {
#pragma unroll
        for (int l = 0; l < 2; l++) {
            if (dvalid[l]) {
                int t  = gidx * 8 + dtl[l];
                int tc = t < T_STEPS ? t : T_STEPS - 1;
                cp_async16(smb + (uint32_t)(((gidx & 3) * 8 * SLOT_F + ddst[l]) * 4),
                           dsrc[l] + (size_t)tc * dstride[l]);
            }
        }
        asm volatile("cp.async.commit_group;\n");
    };

    issue_group(0);
    issue_group(1);
    issue_group(2);

    float4 s0v = *reinterpret_cast<const float4*>(&S0[((size_t)b * NH + i) * NH + c0]);
    float4 s1v = *reinterpret_cast<const float4*>(&S0[((size_t)b * NH + i) * NH + c0 + 4]);
    const float da  = d_alpha[i];
    const float bap = b_alpha[i];

    asm volatile("cp.async.wait_group 2;\n");
    __syncthreads();

    auto K4 = [&](int t, int c) -> float4 {
        return *reinterpret_cast<const float4*>(&sm[(t & (RING - 1)) * SLOT_F + c]);
    };
    auto Q4 = [&](int t, int c) -> float4 {
        return *reinterpret_cast<const float4*>(&sm[(t & (RING - 1)) * SLOT_F + 64 + c]);
    };

    // Prologue: P3_t = s0.k(t), C3_t = s0.q(t) for t = 0,1,2
    float P3_0 = bfly8(dot8(s0v, s1v, K4(0, c0), K4(0, c0 + 4)));
    float P3_1 = bfly8(dot8(s0v, s1v, K4(1, c0), K4(1, c0 + 4)));
    float P3_2 = bfly8(dot8(s0v, s1v, K4(2, c0), K4(2, c0 + 4)));
    float C3_0 = bfly8(dot8(s0v, s1v, Q4(0, c0), Q4(0, c0 + 4)));
    float C3_1 = bfly8(dot8(s0v, s1v, Q4(1, c0), Q4(1, c0 + 4)));
    float C3_2 = bfly8(dot8(s0v, s1v, Q4(2, c0), Q4(2, c0 + 4)));

    float a1 = 1.0f, c1 = 0.0f;
    float M2 = P3_0, M1 = P3_1, P3n = P3_2;
    float N2 = C3_0, N1 = C3_1, C3n = C3_2;

    float* __restrict__ out_bi = out + b * NH + i;

    for (int m = 0; m < T_STEPS / 8; m++) {
        asm volatile("cp.async.wait_group 1;\n");
        __syncthreads();

#pragma unroll
        for (int u = 0; u < 8; u++) {
            const int t = m * 8 + u;
            const int slot = t & (RING - 1);
            const float* sp = &sm[slot * SLOT_F];

            float4 kc0 = K4(t, c0),     kc1 = K4(t, c0 + 4);        // k(t)
            float4 kp0 = K4(t + 3, c0), kp1 = K4(t + 3, c0 + 4);    // k(t+3)
            float4 qp0 = Q4(t + 3, c0), qp1 = Q4(t + 3, c0 + 4);    // q(t+3)
            float  vt  = sp[128 + il];
            float  axb = sp[160 + il] + bap;
            float4 pA  = *reinterpret_cast<const float4*>(&sp[192]);  // KK1,KK2',KK3'',KQ0
            float4 pB  = *reinterpret_cast<const float4*>(&sp[196]);  // KQ1,KQ2',KQ3'',-

            // lag-3 reductions on PRE-update s
            float P3new = bfly8(dot8(s0v, s1v, kp0, kp1));
            float C3new = bfly8(dot8(s0v, s1v, qp0, qp1));

            // recurrence (critical path)
            float rk    = fmaf(a1, M2, c1 * pA.x);
            float z     = fmaf(da, rk, axb);
            float alpha = fsig(z);
            float cc    = (1.0f - alpha) * vt;

            float N3 = fmaf(a1, N2, c1 * pB.x);
            float h  = fmaf(alpha, N3, cc * pA.w);

            float M1n = fmaf(a1, P3n, c1 * pA.z);
            float N1n = fmaf(a1, C3n, c1 * pB.z);
            M2 = fmaf(a1, M1, c1 * pA.y);
            N2 = fmaf(a1, N1, c1 * pB.y);
            M1 = M1n; N1 = N1n; P3n = P3new; C3n = C3new;

            s0v.x = fmaf(alpha, s0v.x, cc * kc0.x);
            s0v.y = fmaf(alpha, s0v.y, cc * kc0.y);
            s0v.z = fmaf(alpha, s0v.z, cc * kc0.z);
            s0v.w = fmaf(alpha, s0v.w, cc * kc0.w);
            s1v.x = fmaf(alpha, s1v.x, cc * kc1.x);
            s1v.y = fmaf(alpha, s1v.y, cc * kc1.y);
            s1v.z = fmaf(alpha, s1v.z, cc * kc1.z);
            s1v.w = fmaf(alpha, s1v.w, cc * kc1.w);

            a1 = alpha; c1 = cc;

            if (j8 == 0) {
                float sg = fsig(h);
                out_bi[(size_t)t * (BATCH * NH)] = h * h * sg;
            }
        }

        issue_group(m + 3);
    }

    float* sf = out + (size_t)T_STEPS * BATCH * NH;
    *reinterpret_cast<float4*>(&sf[((size_t)b * NH + i) * NH + c0])     = s0v;
    *reinterpret_cast<float4*>(&sf[((size_t)b * NH + i) * NH + c0 + 4]) = s1v;
}

extern "C" void kernel_launch(void* const* d_in, const int* in_sizes, int n_in,
                              void* d_out, int out_size)
{
    const float* x  = (const float*)d_in[0];
    const float* S0 = (const float*)d_in[1];
    const float* Wk = (const float*)d_in[2];
    const float* Wv = (const float*)d_in[3];
    const float* Wq = (const float*)d_in[4];
    const float* Wa = (const float*)d_in[5];
    const float* da = (const float*)d_in[6];
    const float* ba = (const float*)d_in[7];
    float* out = (float*)d_out;
    (void)out_size;

    cudaFuncSetAttribute(proj_gemm, cudaFuncAttributeMaxDynamicSharedMemorySize, SMEM_BYTES);
    cudaFuncSetAttribute(scan_kernel, cudaFuncAttributeMaxDynamicSharedMemorySize, SCAN_SMEM);

    proj_gemm<<<M_TOTAL / BM, 512, SMEM_BYTES>>>(x, Wk, Wv, Wq, Wa);
    precomp_kernel<<<M_TOTAL / 8, 256>>>();
    scan_kernel<<<dim3(2, BATCH), 256, SCAN_SMEM>>>(S0, da, ba, out);
}

// round 6
// speedup vs baseline: 1.2866x; 1.2866x over previous
#include <cuda_runtime.h>
#include <cstdint>

// Problem constants
#define T_STEPS 1024
#define BATCH   32
#define DIM     1024
#define NH      64
#define NTOT    256                 // 4 * NH (k | v | q | ax)
#define M_TOTAL (T_STEPS * BATCH)   // 32768

// Scratch: projections Y[m][256], m = t*BATCH+b  (32 MB)
__device__ float g_y[(size_t)M_TOTAL * NTOT];
// Precomputed per-(t,b) dot scalars, 12 floats per slot T:
//  [0..3]: KK2(T+1), KK3(T+1), KK4(T+1), KK1(T)
//  [4..7]: KQ2(T+1), KQ3(T+1), KQ4(T+1), KQ1(T)
//  [8]   : KQ0(T)
// where KKd(S) = k(S-d).k(S), KQd(S) = k(S-d).q(S), KQ0(S) = k(S).q(S)
__device__ float g_pc[(size_t)M_TOTAL * 12];

// ---------------- GEMM (tf32 mma.sync) — R3 version (best measured) ----------------
#define BM 128
#define BK 16
#define STAGES 3
#define XS_STRIDE 20
#define X_TILE_F (BM * XS_STRIDE)
#define W_TILE_F (NTOT * XS_STRIDE)
#define STAGE_F  (X_TILE_F + W_TILE_F)
#define SMEM_BYTES (STAGES * STAGE_F * 4)

__device__ __forceinline__ void cp_async16(uint32_t saddr, const void* gptr) {
    asm volatile("cp.async.cg.shared.global [%0], [%1], 16;\n" :: "r"(saddr), "l"(gptr));
}
__device__ __forceinline__ uint32_t f2tf32(float f) {
    uint32_t r;
    asm("cvt.rna.tf32.f32 %0, %1;" : "=r"(r) : "f"(f));
    return r;
}
__device__ __forceinline__ void mma_tf32(float* c, const uint32_t* a, const uint32_t* b) {
    asm volatile(
        "mma.sync.aligned.m16n8k8.row.col.f32.tf32.tf32.f32 "
        "{%0,%1,%2,%3}, {%4,%5,%6,%7}, {%8,%9}, {%0,%1,%2,%3};"
        : "+f"(c[0]), "+f"(c[1]), "+f"(c[2]), "+f"(c[3])
        : "r"(a[0]), "r"(a[1]), "r"(a[2]), "r"(a[3]), "r"(b[0]), "r"(b[1]));
}

__global__ __launch_bounds__(256, 1)
void proj_gemm(const float* __restrict__ X,
               const float* __restrict__ Wk, const float* __restrict__ Wv,
               const float* __restrict__ Wq, const float* __restrict__ Wa)
{
    extern __shared__ float smem[];
    const int tid = threadIdx.x;
    const int m0  = blockIdx.x * BM;

    const float* wptr[4] = {Wk, Wv, Wq, Wa};

    const float* xg[2];
    uint32_t xs_off[2];
#pragma unroll
    for (int l = 0; l < 2; l++) {
        int f = tid + l * 256;
        int row = f >> 2, c4 = f & 3;
        xg[l] = X + (size_t)(m0 + row) * DIM + c4 * 4;
        xs_off[l] = (uint32_t)(row * XS_STRIDE + c4 * 4);
    }
    const float* wg[4];
    uint32_t ws_off[4];
#pragma unroll
    for (int l = 0; l < 4; l++) {
        int f = tid + l * 256;
        int row = f >> 2, c4 = f & 3;
        wg[l] = wptr[row >> 6] + (size_t)(row & 63) * DIM + c4 * 4;
        ws_off[l] = (uint32_t)(X_TILE_F + row * XS_STRIDE + c4 * 4);
    }
    uint32_t smem_base = (uint32_t)__cvta_generic_to_shared(smem);

    const int lane = tid & 31;
    const int w    = tid >> 5;
    const int g    = lane >> 2;
    const int q    = lane & 3;
    const int wm   = w >> 2;
    const int wn   = w & 3;

    float acc[4][8][4];
#pragma unroll
    for (int mi = 0; mi < 4; mi++)
#pragma unroll
        for (int ni = 0; ni < 8; ni++)
#pragma unroll
            for (int r = 0; r < 4; r++) acc[mi][ni][r] = 0.0f;

    const int NITER = DIM / BK;

#pragma unroll
    for (int s = 0; s < STAGES - 1; s++) {
        uint32_t sb = smem_base + (uint32_t)((s % STAGES) * STAGE_F * 4);
        int koff = s * BK;
#pragma unroll
        for (int l = 0; l < 2; l++) cp_async16(sb + xs_off[l] * 4, xg[l] + koff);
#pragma unroll
        for (int l = 0; l < 4; l++) cp_async16(sb + ws_off[l] * 4, wg[l] + koff);
        asm volatile("cp.async.commit_group;\n");
    }

    for (int k = 0; k < NITER; k++) {
        asm volatile("cp.async.wait_group %0;\n" :: "n"(STAGES - 2));
        __syncthreads();

        int nk = k + STAGES - 1;
        if (nk < NITER) {
            uint32_t sb = smem_base + (uint32_t)((nk % STAGES) * STAGE_F * 4);
            int koff = nk * BK;
#pragma unroll
            for (int l = 0; l < 2; l++) cp_async16(sb + xs_off[l] * 4, xg[l] + koff);
#pragma unroll
            for (int l = 0; l < 4; l++) cp_async16(sb + ws_off[l] * 4, wg[l] + koff);
        }
        asm volatile("cp.async.commit_group;\n");

        const float* Xs = smem + (k % STAGES) * STAGE_F;
        const float* Ws = Xs + X_TILE_F;

#pragma unroll
        for (int kk = 0; kk < BK; kk += 8) {
            uint32_t a[4][4], bf[8][2];
#pragma unroll
            for (int mi = 0; mi < 4; mi++) {
                int r = wm * 64 + mi * 16 + g;
                a[mi][0] = f2tf32(Xs[r * XS_STRIDE + kk + q]);
                a[mi][1] = f2tf32(Xs[(r + 8) * XS_STRIDE + kk + q]);
                a[mi][2] = f2tf32(Xs[r * XS_STRIDE + kk + q + 4]);
                a[mi][3] = f2tf32(Xs[(r + 8) * XS_STRIDE + kk + q + 4]);
            }
#pragma unroll
            for (int ni = 0; ni < 8; ni++) {
                int r = wn * 64 + ni * 8 + g;
                bf[ni][0] = f2tf32(Ws[r * XS_STRIDE + kk + q]);
                bf[ni][1] = f2tf32(Ws[r * XS_STRIDE + kk + q + 4]);
            }
#pragma unroll
            for (int mi = 0; mi < 4; mi++)
#pragma unroll
                for (int ni = 0; ni < 8; ni++)
                    mma_tf32(acc[mi][ni], a[mi], bf[ni]);
        }
    }

#pragma unroll
    for (int mi = 0; mi < 4; mi++) {
#pragma unroll
        for (int ni = 0; ni < 8; ni++) {
            int m = m0 + wm * 64 + mi * 16 + g;
            int c = wn * 64 + ni * 8 + q * 2;
            float2 v0 = make_float2(acc[mi][ni][0], acc[mi][ni][1]);
            float2 v1 = make_float2(acc[mi][ni][2], acc[mi][ni][3]);
            *reinterpret_cast<float2*>(&g_y[(size_t)m * NTOT + c]) = v0;
            *reinterpret_cast<float2*>(&g_y[(size_t)(m + 8) * NTOT + c]) = v1;
        }
    }
}

// ---------------- Precompute k.k / k.q scalars (lag-4 layout) ----------------
__device__ __forceinline__ float wsum32(float v) {
    v += __shfl_xor_sync(0xffffffffu, v, 16);
    v += __shfl_xor_sync(0xffffffffu, v, 8);
    v += __shfl_xor_sync(0xffffffffu, v, 4);
    v += __shfl_xor_sync(0xffffffffu, v, 2);
    v += __shfl_xor_sync(0xffffffffu, v, 1);
    return v;
}
__device__ __forceinline__ float d2(float2 a, float2 b) {
    return fmaf(a.x, b.x, a.y * b.y);
}

__global__ __launch_bounds__(256, 2)
void precomp_kernel()
{
    int gw = (blockIdx.x * blockDim.x + threadIdx.x) >> 5;   // 0..32767
    int lane = threadIdx.x & 31;
    int T = gw >> 5, b = gw & 31;
    int e = lane * 2;

    const float* y = g_y;
    auto ldk = [&](int tt) -> float2 {
        return *reinterpret_cast<const float2*>(&y[(size_t)(tt * BATCH + b) * NTOT + e]);
    };
    auto ldq = [&](int tt) -> float2 {
        return *reinterpret_cast<const float2*>(&y[(size_t)(tt * BATCH + b) * NTOT + 128 + e]);
    };

    int Tp1 = T + 1 < T_STEPS ? T + 1 : T_STEPS - 1;
    int Tm1 = T - 1 >= 0 ? T - 1 : 0;
    int Tm2 = T - 2 >= 0 ? T - 2 : 0;
    int Tm3 = T - 3 >= 0 ? T - 3 : 0;

    float2 kT  = ldk(T),   qT  = ldq(T);
    float2 kp1 = ldk(Tp1), qp1 = ldq(Tp1);
    float2 km1 = ldk(Tm1), km2 = ldk(Tm2), km3 = ldk(Tm3);

    float KK2n = wsum32(d2(km1, kp1));   // KK2(T+1) = k(T-1).k(T+1)
    float KK3n = wsum32(d2(km2, kp1));   // KK3(T+1)
    float KK4n = wsum32(d2(km3, kp1));   // KK4(T+1)
    float KK1  = wsum32(d2(km1, kT));    // KK1(T)
    float KQ2n = wsum32(d2(km1, qp1));   // KQ2(T+1)
    float KQ3n = wsum32(d2(km2, qp1));   // KQ3(T+1)
    float KQ4n = wsum32(d2(km3, qp1));   // KQ4(T+1)
    float KQ1  = wsum32(d2(km1, qT));    // KQ1(T)
    float KQ0  = wsum32(d2(kT,  qT));    // KQ0(T)

    if (lane == 0) {
        float* p = &g_pc[(size_t)gw * 12];
        *reinterpret_cast<float4*>(p)     = make_float4(KK2n, KK3n, KK4n, KK1);
        *reinterpret_cast<float4*>(p + 4) = make_float4(KQ2n, KQ3n, KQ4n, KQ1);
        *reinterpret_cast<float4*>(p + 8) = make_float4(KQ0, 0.f, 0.f, 0.f);
    }
}

// ---------------- Scan v6: lag-4, butterfly software-pipelined over 3 steps ----------------
#define SLOT_F 176           // per-t smem floats: k|q[128] v[16] ax[16] pc[12] pad
#define RINGS  32            // t-slots resident (4 groups of 8)
#define FIELDS 43            // float4 chunks per t (32 kq + 4 v + 4 ax + 3 pc)

__device__ __forceinline__ float bfly8(float v) {
    v += __shfl_xor_sync(0xffffffffu, v, 4);
    v += __shfl_xor_sync(0xffffffffu, v, 2);
    v += __shfl_xor_sync(0xffffffffu, v, 1);
    return v;
}
__device__ __forceinline__ float dot8(float4 a0, float4 a1, float4 b0, float4 b1) {
    float p = a0.x * b0.x;
    p = fmaf(a0.y, b0.y, p); p = fmaf(a0.z, b0.z, p); p = fmaf(a0.w, b0.w, p);
    p = fmaf(a1.x, b1.x, p); p = fmaf(a1.y, b1.y, p);
    p = fmaf(a1.z, b1.z, p); p = fmaf(a1.w, b1.w, p);
    return p;
}
__device__ __forceinline__ float fsig(float z) {
    return __fdividef(1.0f, 1.0f + __expf(-z));
}

__global__ __launch_bounds__(128, 1)
void scan_kernel(const float* __restrict__ S0,
                 const float* __restrict__ d_alpha,
                 const float* __restrict__ b_alpha,
                 float* __restrict__ out)
{
    __shared__ float sm[RINGS * SLOT_F];   // 22528 B

    const int tid  = threadIdx.x;
    const int b    = blockIdx.y;
    const int i0   = blockIdx.x * 16;
    const int lane = tid & 31;
    const int w    = tid >> 5;            // 0..3
    const int r    = lane >> 3;           // row-in-warp 0..3
    const int j8   = lane & 7;            // 8 lanes per row
    const int i    = i0 + w * 4 + r;      // global row
    const int c0   = j8 * 8;              // column base (8 elems/lane)
    const int il   = i - i0;              // 0..15

    // ---- 3 prefetch descriptors/thread (43 float4 fields per t, 344 per group of 8) ----
    const float* dsrc[3];
    int dstride[3], ddst[3], dtl[3];
    bool dvalid[3];
#pragma unroll
    for (int l = 0; l < 3; l++) {
        int c = tid + l * 128;
        dvalid[l] = (c < 8 * FIELDS);
        int tl = c / FIELDS, f = c - tl * FIELDS;
        dtl[l] = tl;
        int srcoff, dstf;
        if (f < 32)      { srcoff = (f < 16 ? f * 4 : 128 + (f - 16) * 4); dstf = f * 4; }
        else if (f < 36) { srcoff = 64  + i0 + (f - 32) * 4; dstf = 128 + (f - 32) * 4; }
        else if (f < 40) { srcoff = 192 + i0 + (f - 36) * 4; dstf = 144 + (f - 36) * 4; }
        else             { srcoff = (f - 40) * 4;            dstf = 160 + (f - 40) * 4; }
        if (f < 40) { dsrc[l] = g_y  + (size_t)b * NTOT + srcoff; dstride[l] = BATCH * NTOT; }
        else        { dsrc[l] = g_pc + (size_t)b * 12   + srcoff; dstride[l] = BATCH * 12;  }
        ddst[l] = tl * SLOT_F + dstf;
    }
    uint32_t smb = (uint32_t)__cvta_generic_to_shared(sm);

    auto issue_group = [&](int gidx) {
#pragma unroll
        for (int l = 0; l < 3; l++) {
            if (dvalid[l]) {
                int t  = gidx * 8 + dtl[l];
                int tc = t < T_STEPS ? t : T_STEPS - 1;
                cp_async16(smb + (uint32_t)(((gidx & 3) * 8 * SLOT_F + ddst[l]) * 4),
                           dsrc[l] + (size_t)tc * dstride[l]);
            }
        }
        asm volatile("cp.async.commit_group;\n");
    };

    issue_group(0);
    issue_group(1);
    issue_group(2);

    float4 s0v = *reinterpret_cast<const float4*>(&S0[((size_t)b * NH + i) * NH + c0]);
    float4 s1v = *reinterpret_cast<const float4*>(&S0[((size_t)b * NH + i) * NH + c0 + 4]);
    const float da  = d_alpha[i];
    const float bap = b_alpha[i];

    asm volatile("cp.async.wait_group 2;\n");
    __syncthreads();

    auto K4 = [&](int t, int c) -> float4 {
        return *reinterpret_cast<const float4*>(&sm[(t & (RINGS - 1)) * SLOT_F + c]);
    };
    auto Q4 = [&](int t, int c) -> float4 {
        return *reinterpret_cast<const float4*>(&sm[(t & (RINGS - 1)) * SLOT_F + 64 + c]);
    };

    // k(t) register ring, 8 slots (read slot u&7 at step t; write k(t+4) to (u+4)&7)
    float4 kr0[8], kr1[8];
#pragma unroll
    for (int j = 0; j < 4; j++) { kr0[j] = K4(j, c0); kr1[j] = K4(j, c0 + 4); }

    // Prologue pipeline init (s(-1)=S0, alpha(<0)=1, c(<0)=0):
    //  KG = full S0.k(0)   (batched G for target 0)
    //  KP = full S0.k(1)   (full P for target 1)
    //  KA2 = level-2 partial of S0.k(2) (target 2)
    //  KA1 = level-1 partial of S0.k(3) (target 3)
    float KG = bfly8(dot8(s0v, s1v, kr0[0], kr1[0]));
    float KP = bfly8(dot8(s0v, s1v, kr0[1], kr1[1]));
    float KA2, KA1;
    {
        float p2 = dot8(s0v, s1v, kr0[2], kr1[2]);
        float l1 = p2 + __shfl_xor_sync(0xffffffffu, p2, 4);
        KA2 = l1 + __shfl_xor_sync(0xffffffffu, l1, 2);
        float p3 = dot8(s0v, s1v, kr0[3], kr1[3]);
        KA1 = p3 + __shfl_xor_sync(0xffffffffu, p3, 4);
    }
    float QG = bfly8(dot8(s0v, s1v, Q4(0, c0), Q4(0, c0 + 4)));
    float QP = bfly8(dot8(s0v, s1v, Q4(1, c0), Q4(1, c0 + 4)));
    float QA2, QA1;
    {
        float p2 = dot8(s0v, s1v, Q4(2, c0), Q4(2, c0 + 4));
        float l1 = p2 + __shfl_xor_sync(0xffffffffu, p2, 4);
        QA2 = l1 + __shfl_xor_sync(0xffffffffu, l1, 2);
        float p3 = dot8(s0v, s1v, Q4(3, c0), Q4(3, c0 + 4));
        QA1 = p3 + __shfl_xor_sync(0xffffffffu, p3, 4);
    }

    float a1 = 1.0f, a2 = 1.0f, a3 = 1.0f;
    float c1 = 0.0f, c2 = 0.0f, c3 = 0.0f;

    float* __restrict__ out_bi = out + b * NH + i;

    for (int m = 0; m < T_STEPS / 8; m++) {
        asm volatile("cp.async.wait_group 1;\n");
        __syncthreads();

#pragma unroll
        for (int u = 0; u < 8; u++) {
            const int t = m * 8 + u;
            const float* sp = &sm[(t & (RINGS - 1)) * SLOT_F];

            // loads for this step
            float4 kp0 = K4(t + 4, c0), kp1 = K4(t + 4, c0 + 4);   // k(t+4)
            float4 qp0 = Q4(t + 4, c0), qp1 = Q4(t + 4, c0 + 4);   // q(t+4)
            float  vt  = sp[128 + il];
            float  axb = sp[144 + il] + bap;
            float4 pA  = *reinterpret_cast<const float4*>(&sp[160]);  // KK2',KK3',KK4',KK1
            float4 pB  = *reinterpret_cast<const float4*>(&sp[164]);  // KQ2',KQ3',KQ4',KQ1
            float  kq0 = sp[168];                                      // KQ0(t)

            // pipelined butterfly stages — all 6 shfls independent
            float pk   = dot8(s0v, s1v, kp0, kp1);                   // launch target t+4
            float KA1n = pk  + __shfl_xor_sync(0xffffffffu, pk,  4); // lvl1 (t+4)
            float KA2n = KA1 + __shfl_xor_sync(0xffffffffu, KA1, 2); // lvl2 (t+3)
            float KPn  = KA2 + __shfl_xor_sync(0xffffffffu, KA2, 1); // full (t+2)
            float pq   = dot8(s0v, s1v, qp0, qp1);
            float QA1n = pq  + __shfl_xor_sync(0xffffffffu, pq,  4);
            float QA2n = QA1 + __shfl_xor_sync(0xffffffffu, QA1, 2);
            float QPn  = QA2 + __shfl_xor_sync(0xffffffffu, QA2, 1);

            // recurrence critical path: final correction for target t
            float rk    = fmaf(a1, KG, c1 * pA.w);
            float z     = fmaf(da, rk, axb);
            float alpha = fsig(z);
            float cc    = (1.0f - alpha) * vt;

            // output h(t)
            float N3 = fmaf(a1, QG, c1 * pB.w);
            float h  = fmaf(alpha, N3, cc * kq0);

            // batched corrections for target t+1 (uses alpha/c of steps t-3..t-1)
            float gk  = fmaf(a3, KP, c3 * pA.z);
            gk        = fmaf(a2, gk, c2 * pA.y);
            float KGn = fmaf(a1, gk, c1 * pA.x);
            float gq  = fmaf(a3, QP, c3 * pB.z);
            gq        = fmaf(a2, gq, c2 * pB.y);
            float QGn = fmaf(a1, gq, c1 * pB.x);

            // state update with k(t) from register ring
            float4 kc0 = kr0[u & 7], kc1 = kr1[u & 7];
            s0v.x = fmaf(alpha, s0v.x, cc * kc0.x);
            s0v.y = fmaf(alpha, s0v.y, cc * kc0.y);
            s0v.z = fmaf(alpha, s0v.z, cc * kc0.z);
            s0v.w = fmaf(alpha, s0v.w, cc * kc0.w);
            s1v.x = fmaf(alpha, s1v.x, cc * kc1.x);
            s1v.y = fmaf(alpha, s1v.y, cc * kc1.y);
            s1v.z = fmaf(alpha, s1v.z, cc * kc1.z);
            s1v.w = fmaf(alpha, s1v.w, cc * kc1.w);
            kr0[(u + 4) & 7] = kp0; kr1[(u + 4) & 7] = kp1;

            // rotate pipelines
            KA1 = KA1n; KA2 = KA2n; KP = KPn; KG = KGn;
            QA1 = QA1n; QA2 = QA2n; QP = QPn; QG = QGn;
            a3 = a2; a2 = a1; a1 = alpha;
            c3 = c2; c2 = c1; c1 = cc;

            if (j8 == 0) {
                float sg = fsig(h);
                out_bi[(size_t)t * (BATCH * NH)] = h * h * sg;
            }
        }

        issue_group(m + 3);
    }

    float* sf = out + (size_t)T_STEPS * BATCH * NH;
    *reinterpret_cast<float4*>(&sf[((size_t)b * NH + i) * NH + c0])     = s0v;
    *reinterpret_cast<float4*>(&sf[((size_t)b * NH + i) * NH + c0 + 4]) = s1v;
}

extern "C" void kernel_launch(void* const* d_in, const int* in_sizes, int n_in,
                              void* d_out, int out_size)
{
    const float* x  = (const float*)d_in[0];
    const float* S0 = (const float*)d_in[1];
    const float* Wk = (const float*)d_in[2];
    const float* Wv = (const float*)d_in[3];
    const float* Wq = (const float*)d_in[4];
    const float* Wa = (const float*)d_in[5];
    const float* da = (const float*)d_in[6];
    const float* ba = (const float*)d_in[7];
    float* out = (float*)d_out;
    (void)out_size;

    cudaFuncSetAttribute(proj_gemm, cudaFuncAttributeMaxDynamicSharedMemorySize, SMEM_BYTES);

    proj_gemm<<<M_TOTAL / BM, 256, SMEM_BYTES>>>(x, Wk, Wv, Wq, Wa);
    precomp_kernel<<<M_TOTAL / 8, 256>>>();
    scan_kernel<<<dim3(4, BATCH), 128>>>(S0, da, ba, out);
}